// round 3
// baseline (speedup 1.0000x reference)
#include <cuda_runtime.h>
#include <cuda_bf16.h>

#define D 4096
#define THREADS 256

// Bank-swizzle map: phys = i ^ g(i[8:5]) with
//   i5 -> b0,  i6 -> b1^b2,  i7 -> b3,  i8 -> b4.
// Injective bank map on each pass's lane-varying bits:
//   P1 lanes vary i{2..6}:   {b2, b3, b4, b0, b1^b2}   rank 5  OK
//   P2 lanes vary i{0,1,6,7,8}: {b0, b1, b1^b2, b3, b4} rank 5  OK
//   P3 lanes vary i{0..4}:   {b0..b4}                   rank 5  OK
// g is GF(2)-linear => swz(base ^ off) = swz(base) ^ swz(off), letting all
// per-access offsets fold to compile-time XOR constants.
__device__ __forceinline__ int gbits(int i) {
    return ((i >> 5) & 1)
         ^ (((i >> 6) & 1) * 6)
         ^ (((i >> 7) & 1) << 3)
         ^ (((i >> 8) & 1) << 4);
}

// 16-point in-register FWHT (4 butterfly stages), fully unrolled.
__device__ __forceinline__ void fwht16(float r[16]) {
#pragma unroll
    for (int h = 1; h < 16; h <<= 1) {
#pragma unroll
        for (int j = 0; j < 16; j++) {
            if (!(j & h)) {
                float a = r[j];
                float b = r[j | h];
                r[j] = a + b;
                r[j | h] = a - b;
            }
        }
    }
}

__global__ __launch_bounds__(THREADS, 8)
void rht_kernel(const float* __restrict__ x,
                const float* __restrict__ signs,
                float* __restrict__ out) {
    __shared__ float s[D];

    const int row = blockIdx.x;
    const int t   = threadIdx.x;

    float r[16];

    // ------- Pass 1: transform bits {0,1,10,11}. Thread t fixes i[9:2]=t. ----
    // float4 loads at i = h*1024 + t*4: lane-contiguous, fully coalesced for
    // both x and signs.
    const float4* __restrict__ xv4 = reinterpret_cast<const float4*>(x + (size_t)row * D);
    const float4* __restrict__ sv4 = reinterpret_cast<const float4*>(signs);
#pragma unroll
    for (int h = 0; h < 4; h++) {
        float4 xv = xv4[(h << 8) + t];
        float4 sv = sv4[(h << 8) + t];
        r[h * 4 + 0] = xv.x * sv.x;   // reg bits: j -> i{0,1}, h -> i{10,11}
        r[h * 4 + 1] = xv.y * sv.y;
        r[h * 4 + 2] = xv.z * sv.z;
        r[h * 4 + 3] = xv.w * sv.w;
    }
    fwht16(r);

    // i = (h<<10)|(t<<2)|j ; g sources (bits 5..8) come only from t<<2.
    // addr = sb1 ^ j  + h*1024  (sb1 bits 10,11 are zero).
    const int sb1 = (t << 2) ^ gbits(t << 2);
#pragma unroll
    for (int h = 0; h < 4; h++) {
#pragma unroll
        for (int j = 0; j < 4; j++) {
            s[(sb1 ^ j) + (h << 10)] = r[h * 4 + j];
        }
    }
    __syncthreads();

    // ------- Pass 2: transform bits {2,3,4,5}. Thread fixes i{0,1,6..11}. ----
    // i = base2 | (k<<2); swz(off_k) = (k<<2) ^ (k>>3)&1  (i5=k3 -> b0).
    const int base2 = ((t >> 2) << 6) | (t & 3);
    const int sb2   = base2 ^ gbits(base2);
#pragma unroll
    for (int k = 0; k < 16; k++) {
        r[k] = s[sb2 ^ ((k << 2) ^ ((k >> 3) & 1))];
    }
    fwht16(r);
#pragma unroll
    for (int k = 0; k < 16; k++) {
        s[sb2 ^ ((k << 2) ^ ((k >> 3) & 1))] = r[k];
    }
    __syncthreads();

    // ------- Pass 3: transform bits {6,7,8,9}. Thread fixes i{0..5,10,11}. ---
    // i = base3 | (k<<6); swz(off_k) = (k<<6) ^ (k0*6) ^ (k1<<3... ) below.
    const int base3 = ((t >> 6) << 10) | (t & 63);
    const int sb3   = base3 ^ ((t >> 5) & 1);   // g source i5 = t5 -> b0
#pragma unroll
    for (int k = 0; k < 16; k++) {
        const int ck = (k << 6) ^ ((k & 1) * 6) ^ ((k & 2) << 2) ^ ((k & 4) << 2);
        r[k] = s[sb3 ^ ck];
    }
    fwht16(r);

    // stores: lanes contiguous in i[4:0] -> one 128B transaction per warp-op.
    // out index = base3 + k*64 folds into STG immediate offsets.
    float* __restrict__ orow = out + (size_t)row * D;
#pragma unroll
    for (int k = 0; k < 16; k++) {
        orow[base3 + (k << 6)] = r[k] * 0.015625f;
    }
}

extern "C" void kernel_launch(void* const* d_in, const int* in_sizes, int n_in,
                              void* d_out, int out_size) {
    const float* x     = (const float*)d_in[0];
    const float* signs = (const float*)d_in[1];
    float* out = (float*)d_out;

    const int n_rows = in_sizes[0] / D;  // 8192
    rht_kernel<<<n_rows, THREADS>>>(x, signs, out);
}

// round 4
// speedup vs baseline: 1.0587x; 1.0587x over previous
#include <cuda_runtime.h>
#include <cuda_bf16.h>

#define D 4096
#define THREADS 256
#define NCTAS 608   // 152 SMs x 4 CTAs: exactly one persistent wave on GB300

// GF(2)-linear bank swizzle (verified R2/R3): phys = i ^ g(i[8:5]),
//   i5 -> b0,  i6 -> b1^b2,  i7 -> b3,  i8 -> b4.
// Injective bank map on each pass's lane-varying bits -> conflict-free.
__device__ __forceinline__ int gbits(int i) {
    return ((i >> 5) & 1)
         ^ (((i >> 6) & 1) * 6)
         ^ (((i >> 7) & 1) << 3)
         ^ (((i >> 8) & 1) << 4);
}

// 16-point in-register FWHT (4 butterfly stages), fully unrolled.
__device__ __forceinline__ void fwht16(float r[16]) {
#pragma unroll
    for (int h = 1; h < 16; h <<= 1) {
#pragma unroll
        for (int j = 0; j < 16; j++) {
            if (!(j & h)) {
                float a = r[j];
                float b = r[j | h];
                r[j] = a + b;
                r[j | h] = a - b;
            }
        }
    }
}

__global__ __launch_bounds__(THREADS, 4)
void rht_kernel(const float* __restrict__ x,
                const float* __restrict__ signs,
                float* __restrict__ out,
                int n_rows) {
    __shared__ float s[2][D];

    const int t = threadIdx.x;

    // ---- per-thread constant bases (all passes) ----
    const int sb1   = (t << 2) ^ gbits(t << 2);
    const int base2 = ((t >> 2) << 6) | (t & 3);
    const int sb2   = base2 ^ gbits(base2);
    const int base3 = ((t >> 6) << 10) | (t & 63);
    const int sb3   = base3 ^ ((t >> 5) & 1);

    // ---- signs: identical for every row -> load ONCE, keep in registers ----
    const float4* __restrict__ sv4 = reinterpret_cast<const float4*>(signs);
    float4 sv[4];
#pragma unroll
    for (int h = 0; h < 4; h++) sv[h] = sv4[(h << 8) + t];

    // ---- prefetch first row ----
    int row = blockIdx.x;
    float4 xa[4];
    {
        const float4* __restrict__ xv4 =
            reinterpret_cast<const float4*>(x + (size_t)row * D);
#pragma unroll
        for (int h = 0; h < 4; h++) xa[h] = xv4[(h << 8) + t];
    }

    int buf = 0;
    while (row < n_rows) {
        float r[16];

        // ------- Pass 1: bits {0,1,10,11} on prefetched data -------
#pragma unroll
        for (int h = 0; h < 4; h++) {
            r[h * 4 + 0] = xa[h].x * sv[h].x;
            r[h * 4 + 1] = xa[h].y * sv[h].y;
            r[h * 4 + 2] = xa[h].z * sv[h].z;
            r[h * 4 + 3] = xa[h].w * sv[h].w;
        }
        fwht16(r);
#pragma unroll
        for (int h = 0; h < 4; h++) {
#pragma unroll
            for (int j = 0; j < 4; j++) {
                s[buf][(sb1 ^ j) + (h << 10)] = r[h * 4 + j];
            }
        }

        // ------- prefetch NEXT row: overlaps with pass 2 + pass 3 -------
        const int nrow = row + NCTAS;
        {
            const int prow = (nrow < n_rows) ? nrow : row;  // safe clamp
            const float4* __restrict__ xv4 =
                reinterpret_cast<const float4*>(x + (size_t)prow * D);
#pragma unroll
            for (int h = 0; h < 4; h++) xa[h] = xv4[(h << 8) + t];
        }

        __syncthreads();   // pass-1 STS visible

        // ------- Pass 2: bits {2,3,4,5} -------
#pragma unroll
        for (int k = 0; k < 16; k++) {
            r[k] = s[buf][sb2 ^ ((k << 2) ^ ((k >> 3) & 1))];
        }
        fwht16(r);
#pragma unroll
        for (int k = 0; k < 16; k++) {
            s[buf][sb2 ^ ((k << 2) ^ ((k >> 3) & 1))] = r[k];
        }
        __syncthreads();   // pass-2 STS visible

        // ------- Pass 3: bits {6,7,8,9} -------
#pragma unroll
        for (int k = 0; k < 16; k++) {
            const int ck = (k << 6) ^ ((k & 1) * 6) ^ ((k & 2) << 2) ^ ((k & 4) << 2);
            r[k] = s[buf][sb3 ^ ck];
        }
        fwht16(r);

        // coalesced stores (lanes contiguous in i[4:0]); normalize by 1/64
        float* __restrict__ orow = out + (size_t)row * D;
#pragma unroll
        for (int k = 0; k < 16; k++) {
            orow[base3 + (k << 6)] = r[k] * 0.015625f;
        }

        row = nrow;
        buf ^= 1;
        // no extra barrier needed: next pass-1 STS targets the OTHER buffer,
        // and barrier A of the next row orders it against all readers.
    }
}

extern "C" void kernel_launch(void* const* d_in, const int* in_sizes, int n_in,
                              void* d_out, int out_size) {
    const float* x     = (const float*)d_in[0];
    const float* signs = (const float*)d_in[1];
    float* out = (float*)d_out;

    const int n_rows = in_sizes[0] / D;  // 8192
    const int grid = (n_rows < NCTAS) ? n_rows : NCTAS;
    rht_kernel<<<grid, THREADS>>>(x, signs, out, n_rows);
}